// round 6
// baseline (speedup 1.0000x reference)
#include <cuda_runtime.h>
#include <cstdint>

#define B_  64
#define P_  2048
#define D_  1024
#define TILE_M 128
#define KC 32
#define NSTAGE (D_ / KC)        /* 32 stages */
#define PITCH 144               /* 9 16B-units/row, odd mod 8 -> conflict-free */
#define A_OFF 0
#define B_OFF (TILE_M * PITCH)  /* 18432 */
#define SMEM_BYTES 33792        /* max(stage 27648, epilogue 128*66*4) */
#define NCTAS ((P_ / TILE_M) * B_)         /* 1024 */

__device__ unsigned int g_key[B_ * B_];    /* order-preserving keys; 0 == -inf */
__device__ unsigned int g_count;           /* last-CTA counter; resets itself  */

__device__ __forceinline__ uint32_t smem_u32(const void* p) {
    uint32_t a;
    asm("{ .reg .u64 t; cvta.to.shared.u64 t, %1; cvt.u32.u64 %0, t; }" : "=r"(a) : "l"(p));
    return a;
}
__device__ __forceinline__ uint32_t pack_bf16x2(float lo_e, float hi_e) {
    uint32_t h;
    asm("cvt.rn.bf16x2.f32 %0, %1, %2;" : "=r"(h) : "f"(hi_e), "f"(lo_e));
    return h;
}
/* 8 fp32 -> hi 16B @hiA, lo 16B @loA */
__device__ __forceinline__ void cvt_sts8(uint32_t hiA, uint32_t loA, float4 v0, float4 v1) {
    uint32_t h0 = pack_bf16x2(v0.x, v0.y);
    uint32_t h1 = pack_bf16x2(v0.z, v0.w);
    uint32_t h2 = pack_bf16x2(v1.x, v1.y);
    uint32_t h3 = pack_bf16x2(v1.z, v1.w);
    uint32_t l0 = pack_bf16x2(v0.x - __uint_as_float(h0 << 16), v0.y - __uint_as_float(h0 & 0xFFFF0000u));
    uint32_t l1 = pack_bf16x2(v0.z - __uint_as_float(h1 << 16), v0.w - __uint_as_float(h1 & 0xFFFF0000u));
    uint32_t l2 = pack_bf16x2(v1.x - __uint_as_float(h2 << 16), v1.y - __uint_as_float(h2 & 0xFFFF0000u));
    uint32_t l3 = pack_bf16x2(v1.z - __uint_as_float(h3 << 16), v1.w - __uint_as_float(h3 & 0xFFFF0000u));
    asm volatile("st.shared.v4.b32 [%0], {%1,%2,%3,%4};" :: "r"(hiA), "r"(h0), "r"(h1), "r"(h2), "r"(h3) : "memory");
    asm volatile("st.shared.v4.b32 [%0], {%1,%2,%3,%4};" :: "r"(loA), "r"(l0), "r"(l1), "r"(l2), "r"(l3) : "memory");
}
__device__ __forceinline__ void ldsm4(uint32_t* r, uint32_t addr) {
    asm volatile("ldmatrix.sync.aligned.m8n8.x4.shared.b16 {%0,%1,%2,%3}, [%4];"
                 : "=r"(r[0]), "=r"(r[1]), "=r"(r[2]), "=r"(r[3]) : "r"(addr));
}
__device__ __forceinline__ void mma16816(float* c, const uint32_t* a, const uint32_t* b) {
    asm volatile(
        "mma.sync.aligned.m16n8k16.row.col.f32.bf16.bf16.f32 "
        "{%0,%1,%2,%3}, {%4,%5,%6,%7}, {%8,%9}, {%0,%1,%2,%3};"
        : "+f"(c[0]), "+f"(c[1]), "+f"(c[2]), "+f"(c[3])
        : "r"(a[0]), "r"(a[1]), "r"(a[2]), "r"(a[3]), "r"(b[0]), "r"(b[1]));
}

/* Grid (16,64), 256 thr. sim[128p x 64c] split-bf16 HMMA; per-col max -> g_key;
   last CTA computes the bidirectional hinge loss and resets globals. */
__global__ __launch_bounds__(256, 2)
void fused_kernel(const float* __restrict__ im, const float* __restrict__ dis,
                  const void* __restrict__ lblRaw, float* __restrict__ out) {
    __shared__ __align__(128) char smem[SMEM_BYTES];
    __shared__ int s_last, s_is64;
    __shared__ float rr[3][8];
    const uint32_t sb = smem_u32(smem);
    const int tid = threadIdx.x, lid = tid & 31, wid = tid >> 5;
    const int wm = wid & 3, wn = wid >> 2;
    const int b = blockIdx.y, pt = blockIdx.x;

    /* A staging: row = tid&127, k16-half = tid>>7 -> 16 floats/thread */
    const int ar = tid & 127, ak = tid >> 7;
    const float* aP = im + ((size_t)(b * P_ + pt * TILE_M + ar)) * D_ + ak * 16;
    const uint32_t aHi = sb + A_OFF + (uint32_t)(ar * PITCH + ak * 32);
    /* B staging: threads 0-127: col = tid&63, k16-half = (tid>>6)&1 -> 16 floats */
    const int bc = tid & 63, bk = (tid >> 6) & 1;
    const bool doB = tid < 128;
    const float* bP = dis + (size_t)bc * D_ + bk * 16;
    const uint32_t bHi = sb + B_OFF + (uint32_t)(bc * PITCH + bk * 32);

    /* ldmatrix lane bases */
    const uint32_t aLd = sb + A_OFF + (uint32_t)((wm * 32 + (lid & 15)) * PITCH + (lid >> 4) * 16);
    const uint32_t bLd = sb + B_OFF + (uint32_t)((wn * 32 + (lid >> 4) * 8 + (lid & 7)) * PITCH
                                                 + ((lid >> 3) & 1) * 16);
    float acc[2][4][4];
    #pragma unroll
    for (int i = 0; i < 2; ++i)
        #pragma unroll
        for (int j = 0; j < 4; ++j)
            #pragma unroll
            for (int k = 0; k < 4; ++k) acc[i][j][k] = 0.f;

    float4 va[4], vb[4];
    #pragma unroll
    for (int i = 0; i < 4; ++i) va[i] = *(const float4*)(aP + i * 4);
    if (doB) {
        #pragma unroll
        for (int i = 0; i < 4; ++i) vb[i] = *(const float4*)(bP + i * 4);
    }

    for (int kt = 0; kt < NSTAGE; ++kt) {
        __syncthreads();   /* previous stage's compute done */
        cvt_sts8(aHi,      aHi + 64,      va[0], va[1]);
        cvt_sts8(aHi + 16, aHi + 64 + 16, va[2], va[3]);
        if (doB) {
            cvt_sts8(bHi,      bHi + 64,      vb[0], vb[1]);
            cvt_sts8(bHi + 16, bHi + 64 + 16, vb[2], vb[3]);
        }
        if (kt + 1 < NSTAGE) {   /* prefetch next stage (consumed next iter) */
            const float* a2 = aP + (kt + 1) * KC;
            #pragma unroll
            for (int i = 0; i < 4; ++i) va[i] = *(const float4*)(a2 + i * 4);
            if (doB) {
                const float* b2 = bP + (kt + 1) * KC;
                #pragma unroll
                for (int i = 0; i < 4; ++i) vb[i] = *(const float4*)(b2 + i * 4);
            }
        }
        __syncthreads();   /* stage visible */

        #pragma unroll
        for (int s = 0; s < 2; ++s) {           /* two k16 sub-chunks */
            uint32_t Bh[2][4], Bl[2][4];
            #pragma unroll
            for (int h = 0; h < 2; ++h) {       /* 16-col halves */
                ldsm4(Bh[h], bLd + h * (16 * PITCH) + s * 32);
                ldsm4(Bl[h], bLd + h * (16 * PITCH) + s * 32 + 64);
            }
            #pragma unroll
            for (int mt = 0; mt < 2; ++mt) {
                uint32_t Ah[4], Al[4];
                ldsm4(Ah, aLd + mt * (16 * PITCH) + s * 32);
                ldsm4(Al, aLd + mt * (16 * PITCH) + s * 32 + 64);
                #pragma unroll
                for (int nt = 0; nt < 4; ++nt) {
                    const uint32_t* bhp = &Bh[nt >> 1][(nt & 1) * 2];
                    const uint32_t* blp = &Bl[nt >> 1][(nt & 1) * 2];
                    mma16816(acc[mt][nt], Ah, bhp);   /* hi*hi */
                    mma16816(acc[mt][nt], Ah, blp);   /* hi*lo */
                    mma16816(acc[mt][nt], Al, bhp);   /* lo*hi */
                }
            }
        }
    }

    /* epilogue: fragments -> smem -> per-column max -> atomicMax */
    __syncthreads();
    float* red = (float*)smem;   /* [128][66] */
    const int g = lid >> 2, t = lid & 3;
    #pragma unroll
    for (int mt = 0; mt < 2; ++mt) {
        const int r0 = wm * 32 + mt * 16 + g;
        #pragma unroll
        for (int nt = 0; nt < 4; ++nt) {
            const int c = wn * 32 + nt * 8 + t * 2;
            red[r0 * 66 + c]           = acc[mt][nt][0];
            red[r0 * 66 + c + 1]       = acc[mt][nt][1];
            red[(r0 + 8) * 66 + c]     = acc[mt][nt][2];
            red[(r0 + 8) * 66 + c + 1] = acc[mt][nt][3];
        }
    }
    __syncthreads();
    if (tid < 64) {
        float m = -3.4e38f;
        #pragma unroll 8
        for (int r = 0; r < TILE_M; ++r) m = fmaxf(m, red[r * 66 + tid]);
        unsigned int k = __float_as_uint(m);
        k = (k & 0x80000000u) ? ~k : (k | 0x80000000u);
        atomicMax(&g_key[b * B_ + tid], k);
    }
    __syncthreads();
    if (tid == 0) {
        __threadfence();
        s_last = (atomicAdd(&g_count, 1u) == NCTAS - 1);
    }
    __syncthreads();
    if (!s_last) return;
    __threadfence();   /* acquire: all producers' g_key writes now visible */

    /* ---- last CTA: decode simMax, hinge loss, reset globals ---- */
    float* sm = (float*)smem;          /* [64][65] */
    int*   lab = (int*)(smem + 64 * 65 * 4);
    for (int e = tid; e < B_ * B_; e += 256) {
        const unsigned int u = g_key[e];
        sm[(e >> 6) * 65 + (e & 63)] =
            __uint_as_float((u & 0x80000000u) ? (u ^ 0x80000000u) : ~u);
    }
    if (tid < 32) {   /* int64 labels (values <64) have zero odd int32 words */
        int odd = ((const int*)lblRaw)[2 * tid + 1];
        unsigned mm = __ballot_sync(0xFFFFFFFFu, odd != 0);
        if (tid == 0) s_is64 = (mm == 0u);
    }
    __syncthreads();
    if (tid < B_)
        lab[tid] = s_is64 ? (int)((const long long*)lblRaw)[tid] : ((const int*)lblRaw)[tid];
    __syncthreads();
    for (int e = tid; e < B_ * B_; e += 256) g_key[e] = 0u;   /* reset */
    if (tid == 0) g_count = 0u;

    float s1 = 0.f, s2 = 0.f, n = 0.f;
    for (int e = tid; e < B_ * B_; e += 256) {
        const int i = e >> 6, j = e & 63;
        if (lab[i] != lab[j]) {
            n += 1.f;
            const float p = sm[i * 65 + i];
            s1 += fmaxf(sm[i * 65 + j] - p + 0.1f, 0.f);
            s2 += fmaxf(sm[j * 65 + i] - p + 0.1f, 0.f);
        }
    }
    #pragma unroll
    for (int o = 16; o > 0; o >>= 1) {
        s1 += __shfl_down_sync(0xFFFFFFFFu, s1, o);
        s2 += __shfl_down_sync(0xFFFFFFFFu, s2, o);
        n  += __shfl_down_sync(0xFFFFFFFFu, n,  o);
    }
    if (lid == 0) { rr[0][wid] = s1; rr[1][wid] = s2; rr[2][wid] = n; }
    __syncthreads();
    if (tid == 0) {
        float a = 0.f, c = 0.f, d = 0.f;
        #pragma unroll
        for (int w = 0; w < 8; ++w) { a += rr[0][w]; c += rr[1][w]; d += rr[2][w]; }
        out[0] = (a + c) / (d + 1e-6f);
    }
}

extern "C" void kernel_launch(void* const* d_in, const int* in_sizes, int n_in,
                              void* d_out, int out_size) {
    (void)in_sizes; (void)n_in; (void)out_size;
    const float* im  = (const float*)d_in[0];
    const float* dis = (const float*)d_in[1];
    const void*  lbl = d_in[2];

    dim3 grid(P_ / TILE_M, B_);
    fused_kernel<<<grid, 256>>>(im, dis, lbl, (float*)d_out);
}

// round 7
// speedup vs baseline: 1.9335x; 1.9335x over previous
#include <cuda_runtime.h>
#include <cstdint>

#define B_  64
#define P_  2048
#define D_  1024
#define TILE_M 128
#define KC 32
#define NSTAGE (D_ / KC)        /* 32 stages */
#define PITCH 144               /* 9 16B-units/row, odd mod 8 -> ldmatrix conflict-free */
#define A_OFF 0
#define B_OFF (TILE_M * PITCH)  /* 18432 */
#define SMEM_BYTES 33792        /* max(stage 27648, epilogue 128*66*4) */
#define NCTAS ((P_ / TILE_M) * B_)         /* 1024 */

__device__ unsigned int g_key[B_ * B_];    /* order-preserving keys; 0 == -inf */
__device__ unsigned int g_count;           /* last-CTA counter; resets itself  */

__device__ __forceinline__ uint32_t smem_u32(const void* p) {
    uint32_t a;
    asm("{ .reg .u64 t; cvta.to.shared.u64 t, %1; cvt.u32.u64 %0, t; }" : "=r"(a) : "l"(p));
    return a;
}
__device__ __forceinline__ uint32_t pack_bf16x2(float lo_e, float hi_e) {
    uint32_t h;
    asm("cvt.rn.bf16x2.f32 %0, %1, %2;" : "=r"(h) : "f"(hi_e), "f"(lo_e));
    return h;
}
/* one float4 (k 4p..4p+3) -> hi 8B @hiA, lo 8B @hiA+16 (next 16B unit) */
__device__ __forceinline__ void cvt_sts4(uint32_t hiA, float4 v) {
    uint32_t h0 = pack_bf16x2(v.x, v.y);
    uint32_t h1 = pack_bf16x2(v.z, v.w);
    uint32_t l0 = pack_bf16x2(v.x - __uint_as_float(h0 << 16),
                              v.y - __uint_as_float(h0 & 0xFFFF0000u));
    uint32_t l1 = pack_bf16x2(v.z - __uint_as_float(h1 << 16),
                              v.w - __uint_as_float(h1 & 0xFFFF0000u));
    asm volatile("st.shared.v2.b32 [%0], {%1,%2};" :: "r"(hiA), "r"(h0), "r"(h1) : "memory");
    asm volatile("st.shared.v2.b32 [%0], {%1,%2};" :: "r"(hiA + 16), "r"(l0), "r"(l1) : "memory");
}
__device__ __forceinline__ void ldsm4(uint32_t* r, uint32_t addr) {
    asm volatile("ldmatrix.sync.aligned.m8n8.x4.shared.b16 {%0,%1,%2,%3}, [%4];"
                 : "=r"(r[0]), "=r"(r[1]), "=r"(r[2]), "=r"(r[3]) : "r"(addr));
}
__device__ __forceinline__ void mma16816(float* c, const uint32_t* a, const uint32_t* b) {
    asm volatile(
        "mma.sync.aligned.m16n8k16.row.col.f32.bf16.bf16.f32 "
        "{%0,%1,%2,%3}, {%4,%5,%6,%7}, {%8,%9}, {%0,%1,%2,%3};"
        : "+f"(c[0]), "+f"(c[1]), "+f"(c[2]), "+f"(c[3])
        : "r"(a[0]), "r"(a[1]), "r"(a[2]), "r"(a[3]), "r"(b[0]), "r"(b[1]));
}

/* Grid (16,64), 256 thr. sim[128p x 64c] split-bf16 HMMA; per-col max -> g_key;
   last CTA computes the bidirectional hinge loss and resets globals.
   Smem layout per row (PITCH=144): 16B units {hi k0-7, lo k0-7, hi k8-15, lo k8-15,
   hi k16-23, lo k16-23, hi k24-31, lo k24-31, pad}. */
__global__ __launch_bounds__(256, 2)
void fused_kernel(const float* __restrict__ im, const float* __restrict__ dis,
                  const void* __restrict__ lblRaw, float* __restrict__ out) {
    __shared__ __align__(128) char smem[SMEM_BYTES];
    __shared__ int s_last, s_is64;
    __shared__ float rr[3][8];
    const uint32_t sb = smem_u32(smem);
    const int tid = threadIdx.x, lid = tid & 31, wid = tid >> 5;
    const int wm = wid & 3, wn = wid >> 2;
    const int b = blockIdx.y, pt = blockIdx.x;

    /* staging slot 0: row = tid>>3, part p = tid&7 (16B of the 128B row-chunk);
       slots j advance rows by +32 (A: j=0..3) / +32 (B: j=0..1). Coalesced:
       8 consecutive lanes cover one full 128B gmem line. */
    const int r0 = tid >> 3, p0 = tid & 7;
    const float* aG = im + ((size_t)(b * P_ + pt * TILE_M + r0)) * D_ + p0 * 4;
    const float* bG = dis + (size_t)r0 * D_ + p0 * 4;
    const uint32_t aS = sb + A_OFF + (uint32_t)(r0 * PITCH + (p0 >> 1) * 32 + (p0 & 1) * 8);
    const uint32_t bS = sb + B_OFF + (uint32_t)(r0 * PITCH + (p0 >> 1) * 32 + (p0 & 1) * 8);

    /* ldmatrix lane bases (hi unit; lo = +16; k-octet-high = +32; sub s = +s*64) */
    const uint32_t aLd = sb + A_OFF + (uint32_t)((wm * 32 + (lid & 15)) * PITCH + (lid >> 4) * 32);
    const uint32_t bLd = sb + B_OFF + (uint32_t)((wn * 32 + (lid >> 4) * 8 + (lid & 7)) * PITCH
                                                 + ((lid >> 3) & 1) * 32);
    float acc[2][4][4];
    #pragma unroll
    for (int i = 0; i < 2; ++i)
        #pragma unroll
        for (int j = 0; j < 4; ++j)
            #pragma unroll
            for (int k = 0; k < 4; ++k) acc[i][j][k] = 0.f;

    float4 va[4], vb[2];
    #pragma unroll
    for (int j = 0; j < 4; ++j) va[j] = *(const float4*)(aG + j * 32 * D_);
    #pragma unroll
    for (int j = 0; j < 2; ++j) vb[j] = *(const float4*)(bG + j * 32 * D_);

    for (int kt = 0; kt < NSTAGE; ++kt) {
        __syncthreads();   /* previous stage's compute done */
        #pragma unroll
        for (int j = 0; j < 4; ++j) cvt_sts4(aS + j * 32 * PITCH, va[j]);
        #pragma unroll
        for (int j = 0; j < 2; ++j) cvt_sts4(bS + j * 32 * PITCH, vb[j]);
        if (kt + 1 < NSTAGE) {   /* prefetch next stage (consumed next iter) */
            const float* a2 = aG + (kt + 1) * KC;
            const float* b2 = bG + (kt + 1) * KC;
            #pragma unroll
            for (int j = 0; j < 4; ++j) va[j] = *(const float4*)(a2 + j * 32 * D_);
            #pragma unroll
            for (int j = 0; j < 2; ++j) vb[j] = *(const float4*)(b2 + j * 32 * D_);
        }
        __syncthreads();   /* stage visible */

        #pragma unroll
        for (int s = 0; s < 2; ++s) {           /* two k16 sub-chunks */
            uint32_t Bh[2][4], Bl[2][4];
            #pragma unroll
            for (int h = 0; h < 2; ++h) {       /* 16-col halves */
                ldsm4(Bh[h], bLd + h * (16 * PITCH) + s * 64);
                ldsm4(Bl[h], bLd + h * (16 * PITCH) + s * 64 + 16);
            }
            #pragma unroll
            for (int mt = 0; mt < 2; ++mt) {
                uint32_t Ah[4], Al[4];
                ldsm4(Ah, aLd + mt * (16 * PITCH) + s * 64);
                ldsm4(Al, aLd + mt * (16 * PITCH) + s * 64 + 16);
                #pragma unroll
                for (int nt = 0; nt < 4; ++nt) {
                    const uint32_t* bhp = &Bh[nt >> 1][(nt & 1) * 2];
                    const uint32_t* blp = &Bl[nt >> 1][(nt & 1) * 2];
                    mma16816(acc[mt][nt], Ah, bhp);   /* hi*hi */
                    mma16816(acc[mt][nt], Ah, blp);   /* hi*lo */
                    mma16816(acc[mt][nt], Al, bhp);   /* lo*hi */
                }
            }
        }
    }

    /* epilogue: fragments -> smem -> per-column max -> atomicMax */
    __syncthreads();
    float* red = (float*)smem;   /* [128][66] */
    const int g = lid >> 2, t = lid & 3;
    #pragma unroll
    for (int mt = 0; mt < 2; ++mt) {
        const int rr0 = wm * 32 + mt * 16 + g;
        #pragma unroll
        for (int nt = 0; nt < 4; ++nt) {
            const int c = wn * 32 + nt * 8 + t * 2;
            red[rr0 * 66 + c]           = acc[mt][nt][0];
            red[rr0 * 66 + c + 1]       = acc[mt][nt][1];
            red[(rr0 + 8) * 66 + c]     = acc[mt][nt][2];
            red[(rr0 + 8) * 66 + c + 1] = acc[mt][nt][3];
        }
    }
    __syncthreads();
    if (tid < 64) {
        float m = -3.4e38f;
        #pragma unroll 8
        for (int r = 0; r < TILE_M; ++r) m = fmaxf(m, red[r * 66 + tid]);
        unsigned int k = __float_as_uint(m);
        k = (k & 0x80000000u) ? ~k : (k | 0x80000000u);
        atomicMax(&g_key[b * B_ + tid], k);
    }
    __syncthreads();
    if (tid == 0) {
        __threadfence();
        s_last = (atomicAdd(&g_count, 1u) == NCTAS - 1);
    }
    __syncthreads();
    if (!s_last) return;
    __threadfence();   /* acquire: all producers' g_key writes now visible */

    /* ---- last CTA: decode simMax, hinge loss, reset globals ---- */
    float* sm = (float*)smem;          /* [64][65] */
    int*   lab = (int*)(smem + 64 * 65 * 4);
    for (int e = tid; e < B_ * B_; e += 256) {
        const unsigned int u = g_key[e];
        sm[(e >> 6) * 65 + (e & 63)] =
            __uint_as_float((u & 0x80000000u) ? (u ^ 0x80000000u) : ~u);
    }
    if (tid < 32) {   /* int64 labels (values <64) have zero odd int32 words */
        int odd = ((const int*)lblRaw)[2 * tid + 1];
        unsigned mm = __ballot_sync(0xFFFFFFFFu, odd != 0);
        if (tid == 0) s_is64 = (mm == 0u);
    }
    __syncthreads();
    if (tid < B_)
        lab[tid] = s_is64 ? (int)((const long long*)lblRaw)[tid] : ((const int*)lblRaw)[tid];
    __syncthreads();
    for (int e = tid; e < B_ * B_; e += 256) g_key[e] = 0u;   /* reset */
    if (tid == 0) g_count = 0u;

    float s1 = 0.f, s2 = 0.f, n = 0.f;
    for (int e = tid; e < B_ * B_; e += 256) {
        const int i = e >> 6, j = e & 63;
        if (lab[i] != lab[j]) {
            n += 1.f;
            const float p = sm[i * 65 + i];
            s1 += fmaxf(sm[i * 65 + j] - p + 0.1f, 0.f);
            s2 += fmaxf(sm[j * 65 + i] - p + 0.1f, 0.f);
        }
    }
    #pragma unroll
    for (int o = 16; o > 0; o >>= 1) {
        s1 += __shfl_down_sync(0xFFFFFFFFu, s1, o);
        s2 += __shfl_down_sync(0xFFFFFFFFu, s2, o);
        n  += __shfl_down_sync(0xFFFFFFFFu, n,  o);
    }
    if (lid == 0) { rr[0][wid] = s1; rr[1][wid] = s2; rr[2][wid] = n; }
    __syncthreads();
    if (tid == 0) {
        float a = 0.f, c = 0.f, d = 0.f;
        #pragma unroll
        for (int w = 0; w < 8; ++w) { a += rr[0][w]; c += rr[1][w]; d += rr[2][w]; }
        out[0] = (a + c) / (d + 1e-6f);
    }
}

extern "C" void kernel_launch(void* const* d_in, const int* in_sizes, int n_in,
                              void* d_out, int out_size) {
    (void)in_sizes; (void)n_in; (void)out_size;
    const float* im  = (const float*)d_in[0];
    const float* dis = (const float*)d_in[1];
    const void*  lbl = d_in[2];

    dim3 grid(P_ / TILE_M, B_);
    fused_kernel<<<grid, 256>>>(im, dis, lbl, (float*)d_out);
}

// round 8
// speedup vs baseline: 2.0202x; 1.0449x over previous
#include <cuda_runtime.h>
#include <cstdint>

#define B_  64
#define P_  2048
#define D_  1024
#define TILE_M 128
#define KC 32
#define NSTAGE (D_ / KC)        /* 32 stages */
#define PITCH 144               /* 9 16B-units/row, odd mod 8 -> ldmatrix conflict-free */
#define A_OFF 0
#define B_OFF (TILE_M * PITCH)  /* 18432 */
#define STAGE_B 27648           /* one buffer: A 18432 + B 9216 */
#define SMEM_BYTES (2 * STAGE_B)           /* 55296 dynamic */
#define NCTAS ((P_ / TILE_M) * B_)         /* 1024 */

__device__ unsigned int g_key[B_ * B_];    /* order-preserving keys; 0 == -inf */
__device__ unsigned int g_count;           /* last-CTA counter; resets itself  */

__device__ __forceinline__ uint32_t smem_u32(const void* p) {
    uint32_t a;
    asm("{ .reg .u64 t; cvta.to.shared.u64 t, %1; cvt.u32.u64 %0, t; }" : "=r"(a) : "l"(p));
    return a;
}
__device__ __forceinline__ uint32_t pack_bf16x2(float lo_e, float hi_e) {
    uint32_t h;
    asm("cvt.rn.bf16x2.f32 %0, %1, %2;" : "=r"(h) : "f"(hi_e), "f"(lo_e));
    return h;
}
/* one float4 (k 4p..4p+3) -> hi 8B @hiA, lo 8B @hiA+16 (next 16B unit) */
__device__ __forceinline__ void cvt_sts4(uint32_t hiA, float4 v) {
    uint32_t h0 = pack_bf16x2(v.x, v.y);
    uint32_t h1 = pack_bf16x2(v.z, v.w);
    uint32_t l0 = pack_bf16x2(v.x - __uint_as_float(h0 << 16),
                              v.y - __uint_as_float(h0 & 0xFFFF0000u));
    uint32_t l1 = pack_bf16x2(v.z - __uint_as_float(h1 << 16),
                              v.w - __uint_as_float(h1 & 0xFFFF0000u));
    asm volatile("st.shared.v2.b32 [%0], {%1,%2};" :: "r"(hiA), "r"(h0), "r"(h1) : "memory");
    asm volatile("st.shared.v2.b32 [%0], {%1,%2};" :: "r"(hiA + 16), "r"(l0), "r"(l1) : "memory");
}
__device__ __forceinline__ void ldsm4(uint32_t* r, uint32_t addr) {
    asm volatile("ldmatrix.sync.aligned.m8n8.x4.shared.b16 {%0,%1,%2,%3}, [%4];"
                 : "=r"(r[0]), "=r"(r[1]), "=r"(r[2]), "=r"(r[3]) : "r"(addr));
}
__device__ __forceinline__ void mma16816(float* c, const uint32_t* a, const uint32_t* b) {
    asm volatile(
        "mma.sync.aligned.m16n8k16.row.col.f32.bf16.bf16.f32 "
        "{%0,%1,%2,%3}, {%4,%5,%6,%7}, {%8,%9}, {%0,%1,%2,%3};"
        : "+f"(c[0]), "+f"(c[1]), "+f"(c[2]), "+f"(c[3])
        : "r"(a[0]), "r"(a[1]), "r"(a[2]), "r"(a[3]), "r"(b[0]), "r"(b[1]));
}

/* Grid (16,64), 256 thr. sim[128p x 64c] split-bf16 HMMA, double-buffered smem,
   one barrier/stage; per-col max -> g_key; last CTA computes the hinge loss.
   Row layout (PITCH=144): 16B units {hi k0-7, lo k0-7, hi k8-15, lo k8-15,
   hi k16-23, lo k16-23, hi k24-31, lo k24-31, pad}. */
__global__ __launch_bounds__(256, 2)
void fused_kernel(const float* __restrict__ im, const float* __restrict__ dis,
                  const void* __restrict__ lblRaw, float* __restrict__ out) {
    extern __shared__ __align__(128) char smem[];
    __shared__ int s_last, s_is64;
    __shared__ float rr[3][8];
    const uint32_t sb = smem_u32(smem);
    const int tid = threadIdx.x, lid = tid & 31, wid = tid >> 5;
    const int wm = wid & 3, wn = wid >> 2;
    const int b = blockIdx.y, pt = blockIdx.x;

    /* staging: row = tid>>3, part p = tid&7; 8 lanes cover one 128B gmem line */
    const int r0 = tid >> 3, p0 = tid & 7;
    const float* aG = im + ((size_t)(b * P_ + pt * TILE_M + r0)) * D_ + p0 * 4;
    const float* bG = dis + (size_t)r0 * D_ + p0 * 4;
    const uint32_t aS = sb + A_OFF + (uint32_t)(r0 * PITCH + (p0 >> 1) * 32 + (p0 & 1) * 8);
    const uint32_t bS = sb + B_OFF + (uint32_t)(r0 * PITCH + (p0 >> 1) * 32 + (p0 & 1) * 8);

    /* ldmatrix lane bases (hi unit; lo = +16; k-octet-high = +32; sub s = +s*64) */
    const uint32_t aLd = sb + A_OFF + (uint32_t)((wm * 32 + (lid & 15)) * PITCH + (lid >> 4) * 32);
    const uint32_t bLd = sb + B_OFF + (uint32_t)((wn * 32 + (lid >> 4) * 8 + (lid & 7)) * PITCH
                                                 + ((lid >> 3) & 1) * 32);
    float acc[2][4][4];
    #pragma unroll
    for (int i = 0; i < 2; ++i)
        #pragma unroll
        for (int j = 0; j < 4; ++j)
            #pragma unroll
            for (int k = 0; k < 4; ++k) acc[i][j][k] = 0.f;

    float4 va[4], vb[2];

    /* prologue: stage 0 -> buf0; prefetch stage 1 into regs */
    #pragma unroll
    for (int j = 0; j < 4; ++j) va[j] = *(const float4*)(aG + j * 32 * D_);
    #pragma unroll
    for (int j = 0; j < 2; ++j) vb[j] = *(const float4*)(bG + j * 32 * D_);
    #pragma unroll
    for (int j = 0; j < 4; ++j) cvt_sts4(aS + j * 32 * PITCH, va[j]);
    #pragma unroll
    for (int j = 0; j < 2; ++j) cvt_sts4(bS + j * 32 * PITCH, vb[j]);
    #pragma unroll
    for (int j = 0; j < 4; ++j) va[j] = *(const float4*)(aG + KC + j * 32 * D_);
    #pragma unroll
    for (int j = 0; j < 2; ++j) vb[j] = *(const float4*)(bG + KC + j * 32 * D_);
    __syncthreads();

    for (int kt = 0; kt < NSTAGE; ++kt) {
        const uint32_t cur = (uint32_t)((kt & 1) * STAGE_B);
        const uint32_t nxt = (uint32_t)(((kt + 1) & 1) * STAGE_B);

        /* store stage kt+1 (regs loaded last iter) into the other buffer */
        if (kt + 1 < NSTAGE) {
            #pragma unroll
            for (int j = 0; j < 4; ++j) cvt_sts4(nxt + aS + j * 32 * PITCH, va[j]);
            #pragma unroll
            for (int j = 0; j < 2; ++j) cvt_sts4(nxt + bS + j * 32 * PITCH, vb[j]);
        }
        /* prefetch stage kt+2 */
        if (kt + 2 < NSTAGE) {
            const float* a2 = aG + (kt + 2) * KC;
            const float* b2 = bG + (kt + 2) * KC;
            #pragma unroll
            for (int j = 0; j < 4; ++j) va[j] = *(const float4*)(a2 + j * 32 * D_);
            #pragma unroll
            for (int j = 0; j < 2; ++j) vb[j] = *(const float4*)(b2 + j * 32 * D_);
        }

        /* compute stage kt from cur buffer (overlaps the STS/LDG above) */
        #pragma unroll
        for (int s = 0; s < 2; ++s) {           /* two k16 sub-chunks */
            uint32_t Bh[2][4], Bl[2][4];
            #pragma unroll
            for (int h = 0; h < 2; ++h) {       /* 16-col halves */
                ldsm4(Bh[h], cur + bLd + h * (16 * PITCH) + s * 64);
                ldsm4(Bl[h], cur + bLd + h * (16 * PITCH) + s * 64 + 16);
            }
            #pragma unroll
            for (int mt = 0; mt < 2; ++mt) {
                uint32_t Ah[4], Al[4];
                ldsm4(Ah, cur + aLd + mt * (16 * PITCH) + s * 64);
                ldsm4(Al, cur + aLd + mt * (16 * PITCH) + s * 64 + 16);
                #pragma unroll
                for (int nt = 0; nt < 4; ++nt) {
                    const uint32_t* bhp = &Bh[nt >> 1][(nt & 1) * 2];
                    const uint32_t* blp = &Bl[nt >> 1][(nt & 1) * 2];
                    mma16816(acc[mt][nt], Ah, bhp);   /* hi*hi */
                    mma16816(acc[mt][nt], Ah, blp);   /* hi*lo */
                    mma16816(acc[mt][nt], Al, bhp);   /* lo*hi */
                }
            }
        }
        __syncthreads();   /* reads of cur done; writes to nxt visible */
    }

    /* epilogue: fragments -> smem -> per-column max -> atomicMax */
    float* red = (float*)smem;   /* [128][66] = 33792 <= 55296 */
    const int g = lid >> 2, t = lid & 3;
    #pragma unroll
    for (int mt = 0; mt < 2; ++mt) {
        const int rr0 = wm * 32 + mt * 16 + g;
        #pragma unroll
        for (int nt = 0; nt < 4; ++nt) {
            const int c = wn * 32 + nt * 8 + t * 2;
            red[rr0 * 66 + c]           = acc[mt][nt][0];
            red[rr0 * 66 + c + 1]       = acc[mt][nt][1];
            red[(rr0 + 8) * 66 + c]     = acc[mt][nt][2];
            red[(rr0 + 8) * 66 + c + 1] = acc[mt][nt][3];
        }
    }
    __syncthreads();
    if (tid < 64) {
        float m = -3.4e38f;
        #pragma unroll 8
        for (int r = 0; r < TILE_M; ++r) m = fmaxf(m, red[r * 66 + tid]);
        unsigned int k = __float_as_uint(m);
        k = (k & 0x80000000u) ? ~k : (k | 0x80000000u);
        atomicMax(&g_key[b * B_ + tid], k);
    }
    __syncthreads();
    if (tid == 0) {
        __threadfence();
        s_last = (atomicAdd(&g_count, 1u) == NCTAS - 1);
    }
    __syncthreads();
    if (!s_last) return;
    __threadfence();   /* acquire: all producers' g_key writes now visible */

    /* ---- last CTA: decode simMax, hinge loss, reset globals ---- */
    float* sm = (float*)smem;          /* [64][65] */
    int*   lab = (int*)(smem + 64 * 65 * 4);
    for (int e = tid; e < B_ * B_; e += 256) {
        const unsigned int u = g_key[e];
        sm[(e >> 6) * 65 + (e & 63)] =
            __uint_as_float((u & 0x80000000u) ? (u ^ 0x80000000u) : ~u);
    }
    if (tid < 32) {   /* int64 labels (values <64) have zero odd int32 words */
        int odd = ((const int*)lblRaw)[2 * tid + 1];
        unsigned mm = __ballot_sync(0xFFFFFFFFu, odd != 0);
        if (tid == 0) s_is64 = (mm == 0u);
    }
    __syncthreads();
    if (tid < B_)
        lab[tid] = s_is64 ? (int)((const long long*)lblRaw)[tid] : ((const int*)lblRaw)[tid];
    __syncthreads();
    for (int e = tid; e < B_ * B_; e += 256) g_key[e] = 0u;   /* reset */
    if (tid == 0) g_count = 0u;

    float s1 = 0.f, s2 = 0.f, n = 0.f;
    for (int e = tid; e < B_ * B_; e += 256) {
        const int i = e >> 6, j = e & 63;
        if (lab[i] != lab[j]) {
            n += 1.f;
            const float p = sm[i * 65 + i];
            s1 += fmaxf(sm[i * 65 + j] - p + 0.1f, 0.f);
            s2 += fmaxf(sm[j * 65 + i] - p + 0.1f, 0.f);
        }
    }
    #pragma unroll
    for (int o = 16; o > 0; o >>= 1) {
        s1 += __shfl_down_sync(0xFFFFFFFFu, s1, o);
        s2 += __shfl_down_sync(0xFFFFFFFFu, s2, o);
        n  += __shfl_down_sync(0xFFFFFFFFu, n,  o);
    }
    if (lid == 0) { rr[0][wid] = s1; rr[1][wid] = s2; rr[2][wid] = n; }
    __syncthreads();
    if (tid == 0) {
        float a = 0.f, c = 0.f, d = 0.f;
        #pragma unroll
        for (int w = 0; w < 8; ++w) { a += rr[0][w]; c += rr[1][w]; d += rr[2][w]; }
        out[0] = (a + c) / (d + 1e-6f);
    }
}

extern "C" void kernel_launch(void* const* d_in, const int* in_sizes, int n_in,
                              void* d_out, int out_size) {
    (void)in_sizes; (void)n_in; (void)out_size;
    const float* im  = (const float*)d_in[0];
    const float* dis = (const float*)d_in[1];
    const void*  lbl = d_in[2];

    cudaFuncSetAttribute(fused_kernel, cudaFuncAttributeMaxDynamicSharedMemorySize, SMEM_BYTES);
    dim3 grid(P_ / TILE_M, B_);
    fused_kernel<<<grid, 256, SMEM_BYTES>>>(im, dis, lbl, (float*)d_out);
}

// round 9
// speedup vs baseline: 2.0323x; 1.0060x over previous
#include <cuda_runtime.h>
#include <cstdint>

#define B_  64
#define P_  2048
#define D_  1024
#define TILE_M 128
#define KC 32
#define NSTAGE (D_ / KC)        /* 32 stages */
#define PITCH 144               /* 9 16B-units/row, odd mod 8 -> ldmatrix conflict-free */
#define A_OFF 0
#define B_OFF (TILE_M * PITCH)  /* 18432 */
#define STAGE_B 27648           /* one buffer: A 18432 + B 9216 */
#define SMEM_BYTES (2 * STAGE_B)           /* 55296 dynamic */
#define NCTAS ((P_ / TILE_M) * B_)         /* 1024 */

__device__ unsigned int g_key[B_ * B_];    /* order-preserving keys; 0 == -inf */
__device__ unsigned int g_count;           /* last-CTA counter; resets itself  */

__device__ __forceinline__ uint32_t smem_u32(const void* p) {
    uint32_t a;
    asm("{ .reg .u64 t; cvta.to.shared.u64 t, %1; cvt.u32.u64 %0, t; }" : "=r"(a) : "l"(p));
    return a;
}
__device__ __forceinline__ uint32_t pack_bf16x2(float lo_e, float hi_e) {
    uint32_t h;
    asm("cvt.rn.bf16x2.f32 %0, %1, %2;" : "=r"(h) : "f"(hi_e), "f"(lo_e));
    return h;
}
/* one float4 (k 4p..4p+3) -> hi 8B @hiA, lo 8B @hiA+16 (next 16B unit) */
__device__ __forceinline__ void cvt_sts4(uint32_t hiA, float4 v) {
    uint32_t h0 = pack_bf16x2(v.x, v.y);
    uint32_t h1 = pack_bf16x2(v.z, v.w);
    uint32_t l0 = pack_bf16x2(v.x - __uint_as_float(h0 << 16),
                              v.y - __uint_as_float(h0 & 0xFFFF0000u));
    uint32_t l1 = pack_bf16x2(v.z - __uint_as_float(h1 << 16),
                              v.w - __uint_as_float(h1 & 0xFFFF0000u));
    asm volatile("st.shared.v2.b32 [%0], {%1,%2};" :: "r"(hiA), "r"(h0), "r"(h1) : "memory");
    asm volatile("st.shared.v2.b32 [%0], {%1,%2};" :: "r"(hiA + 16), "r"(l0), "r"(l1) : "memory");
}
__device__ __forceinline__ void ldsm4(uint32_t* r, uint32_t addr) {
    asm volatile("ldmatrix.sync.aligned.m8n8.x4.shared.b16 {%0,%1,%2,%3}, [%4];"
                 : "=r"(r[0]), "=r"(r[1]), "=r"(r[2]), "=r"(r[3]) : "r"(addr));
}
__device__ __forceinline__ void mma16816(float* c, const uint32_t* a, const uint32_t* b) {
    asm volatile(
        "mma.sync.aligned.m16n8k16.row.col.f32.bf16.bf16.f32 "
        "{%0,%1,%2,%3}, {%4,%5,%6,%7}, {%8,%9}, {%0,%1,%2,%3};"
        : "+f"(c[0]), "+f"(c[1]), "+f"(c[2]), "+f"(c[3])
        : "r"(a[0]), "r"(a[1]), "r"(a[2]), "r"(a[3]), "r"(b[0]), "r"(b[1]));
}

/* Grid (16,64), 256 thr. sim[128p x 64c] split-bf16 HMMA, double-buffered smem,
   term-major MMA ordering (8 independent accs between same-acc MMAs).
   Row layout (PITCH=144): 16B units {hi k0-7, lo k0-7, hi k8-15, lo k8-15,
   hi k16-23, lo k16-23, hi k24-31, lo k24-31, pad}. */
__global__ __launch_bounds__(256, 2)
void fused_kernel(const float* __restrict__ im, const float* __restrict__ dis,
                  const void* __restrict__ lblRaw, float* __restrict__ out) {
    extern __shared__ __align__(128) char smem[];
    __shared__ int s_last, s_is64;
    __shared__ float rr[3][8];
    const uint32_t sb = smem_u32(smem);
    const int tid = threadIdx.x, lid = tid & 31, wid = tid >> 5;
    const int wm = wid & 3, wn = wid >> 2;
    const int b = blockIdx.y, pt = blockIdx.x;

    /* staging: row = tid>>3, part p = tid&7; 8 lanes cover one 128B gmem line */
    const int r0 = tid >> 3, p0 = tid & 7;
    const float* aG = im + ((size_t)(b * P_ + pt * TILE_M + r0)) * D_ + p0 * 4;
    const float* bG = dis + (size_t)r0 * D_ + p0 * 4;
    const uint32_t aS = sb + A_OFF + (uint32_t)(r0 * PITCH + (p0 >> 1) * 32 + (p0 & 1) * 8);
    const uint32_t bS = sb + B_OFF + (uint32_t)(r0 * PITCH + (p0 >> 1) * 32 + (p0 & 1) * 8);

    /* ldmatrix lane bases (hi unit; lo = +16; k-octet-high = +32; sub s = +s*64) */
    const uint32_t aLd = sb + A_OFF + (uint32_t)((wm * 32 + (lid & 15)) * PITCH + (lid >> 4) * 32);
    const uint32_t bLd = sb + B_OFF + (uint32_t)((wn * 32 + (lid >> 4) * 8 + (lid & 7)) * PITCH
                                                 + ((lid >> 3) & 1) * 32);
    float acc[2][4][4];
    #pragma unroll
    for (int i = 0; i < 2; ++i)
        #pragma unroll
        for (int j = 0; j < 4; ++j)
            #pragma unroll
            for (int k = 0; k < 4; ++k) acc[i][j][k] = 0.f;

    float4 va[4], vb[2];

    /* prologue: stage 0 -> buf0; prefetch stage 1 into regs */
    #pragma unroll
    for (int j = 0; j < 4; ++j) va[j] = *(const float4*)(aG + j * 32 * D_);
    #pragma unroll
    for (int j = 0; j < 2; ++j) vb[j] = *(const float4*)(bG + j * 32 * D_);
    #pragma unroll
    for (int j = 0; j < 4; ++j) cvt_sts4(aS + j * 32 * PITCH, va[j]);
    #pragma unroll
    for (int j = 0; j < 2; ++j) cvt_sts4(bS + j * 32 * PITCH, vb[j]);
    #pragma unroll
    for (int j = 0; j < 4; ++j) va[j] = *(const float4*)(aG + KC + j * 32 * D_);
    #pragma unroll
    for (int j = 0; j < 2; ++j) vb[j] = *(const float4*)(bG + KC + j * 32 * D_);
    __syncthreads();

    for (int kt = 0; kt < NSTAGE; ++kt) {
        const uint32_t cur = (uint32_t)((kt & 1) * STAGE_B);
        const uint32_t nxt = (uint32_t)(((kt + 1) & 1) * STAGE_B);

        /* store stage kt+1 (regs loaded last iter) into the other buffer */
        if (kt + 1 < NSTAGE) {
            #pragma unroll
            for (int j = 0; j < 4; ++j) cvt_sts4(nxt + aS + j * 32 * PITCH, va[j]);
            #pragma unroll
            for (int j = 0; j < 2; ++j) cvt_sts4(nxt + bS + j * 32 * PITCH, vb[j]);
        }
        /* prefetch stage kt+2 */
        if (kt + 2 < NSTAGE) {
            const float* a2 = aG + (kt + 2) * KC;
            const float* b2 = bG + (kt + 2) * KC;
            #pragma unroll
            for (int j = 0; j < 4; ++j) va[j] = *(const float4*)(a2 + j * 32 * D_);
            #pragma unroll
            for (int j = 0; j < 2; ++j) vb[j] = *(const float4*)(b2 + j * 32 * D_);
        }

        /* compute stage kt: per k16 sub-chunk load ALL fragments, then issue
           term-major passes -> 8 independent MMAs between same-acc MMAs */
        #pragma unroll
        for (int s = 0; s < 2; ++s) {
            uint32_t Ah[2][4], Al[2][4], Bh[2][4], Bl[2][4];
            #pragma unroll
            for (int mt = 0; mt < 2; ++mt) {
                ldsm4(Ah[mt], cur + aLd + mt * (16 * PITCH) + s * 64);
                ldsm4(Al[mt], cur + aLd + mt * (16 * PITCH) + s * 64 + 16);
            }
            #pragma unroll
            for (int h = 0; h < 2; ++h) {
                ldsm4(Bh[h], cur + bLd + h * (16 * PITCH) + s * 64);
                ldsm4(Bl[h], cur + bLd + h * (16 * PITCH) + s * 64 + 16);
            }
            /* pass 1: hi*hi */
            #pragma unroll
            for (int mt = 0; mt < 2; ++mt)
                #pragma unroll
                for (int nt = 0; nt < 4; ++nt)
                    mma16816(acc[mt][nt], Ah[mt], &Bh[nt >> 1][(nt & 1) * 2]);
            /* pass 2: hi*lo */
            #pragma unroll
            for (int mt = 0; mt < 2; ++mt)
                #pragma unroll
                for (int nt = 0; nt < 4; ++nt)
                    mma16816(acc[mt][nt], Ah[mt], &Bl[nt >> 1][(nt & 1) * 2]);
            /* pass 3: lo*hi */
            #pragma unroll
            for (int mt = 0; mt < 2; ++mt)
                #pragma unroll
                for (int nt = 0; nt < 4; ++nt)
                    mma16816(acc[mt][nt], Al[mt], &Bh[nt >> 1][(nt & 1) * 2]);
        }
        __syncthreads();   /* reads of cur done; writes to nxt visible */
    }

    /* epilogue: fragments -> smem -> per-column max -> atomicMax */
    float* red = (float*)smem;   /* [128][66] = 33792 <= 55296 */
    const int g = lid >> 2, t = lid & 3;
    #pragma unroll
    for (int mt = 0; mt < 2; ++mt) {
        const int rr0 = wm * 32 + mt * 16 + g;
        #pragma unroll
        for (int nt = 0; nt < 4; ++nt) {
            const int c = wn * 32 + nt * 8 + t * 2;
            red[rr0 * 66 + c]           = acc[mt][nt][0];
            red[rr0 * 66 + c + 1]       = acc[mt][nt][1];
            red[(rr0 + 8) * 66 + c]     = acc[mt][nt][2];
            red[(rr0 + 8) * 66 + c + 1] = acc[mt][nt][3];
        }
    }
    __syncthreads();
    if (tid < 64) {
        float m = -3.4e38f;
        #pragma unroll 8
        for (int r = 0; r < TILE_M; ++r) m = fmaxf(m, red[r * 66 + tid]);
        unsigned int k = __float_as_uint(m);
        k = (k & 0x80000000u) ? ~k : (k | 0x80000000u);
        atomicMax(&g_key[b * B_ + tid], k);
    }
    __syncthreads();
    if (tid == 0) {
        __threadfence();
        s_last = (atomicAdd(&g_count, 1u) == NCTAS - 1);
    }
    __syncthreads();
    if (!s_last) return;
    __threadfence();   /* acquire: all producers' g_key writes now visible */

    /* ---- last CTA: decode simMax, hinge loss, reset globals ---- */
    float* sm = (float*)smem;          /* [64][65] */
    int*   lab = (int*)(smem + 64 * 65 * 4);
    for (int e = tid; e < B_ * B_; e += 256) {
        const unsigned int u = g_key[e];
        sm[(e >> 6) * 65 + (e & 63)] =
            __uint_as_float((u & 0x80000000u) ? (u ^ 0x80000000u) : ~u);
    }
    if (tid < 32) {   /* int64 labels (values <64) have zero odd int32 words */
        int odd = ((const int*)lblRaw)[2 * tid + 1];
        unsigned mm = __ballot_sync(0xFFFFFFFFu, odd != 0);
        if (tid == 0) s_is64 = (mm == 0u);
    }
    __syncthreads();
    if (tid < B_)
        lab[tid] = s_is64 ? (int)((const long long*)lblRaw)[tid] : ((const int*)lblRaw)[tid];
    __syncthreads();
    for (int e = tid; e < B_ * B_; e += 256) g_key[e] = 0u;   /* reset */
    if (tid == 0) g_count = 0u;

    float s1 = 0.f, s2 = 0.f, n = 0.f;
    for (int e = tid; e < B_ * B_; e += 256) {
        const int i = e >> 6, j = e & 63;
        if (lab[i] != lab[j]) {
            n += 1.f;
            const float p = sm[i * 65 + i];
            s1 += fmaxf(sm[i * 65 + j] - p + 0.1f, 0.f);
            s2 += fmaxf(sm[j * 65 + i] - p + 0.1f, 0.f);
        }
    }
    #pragma unroll
    for (int o = 16; o > 0; o >>= 1) {
        s1 += __shfl_down_sync(0xFFFFFFFFu, s1, o);
        s2 += __shfl_down_sync(0xFFFFFFFFu, s2, o);
        n  += __shfl_down_sync(0xFFFFFFFFu, n,  o);
    }
    if (lid == 0) { rr[0][wid] = s1; rr[1][wid] = s2; rr[2][wid] = n; }
    __syncthreads();
    if (tid == 0) {
        float a = 0.f, c = 0.f, d = 0.f;
        #pragma unroll
        for (int w = 0; w < 8; ++w) { a += rr[0][w]; c += rr[1][w]; d += rr[2][w]; }
        out[0] = (a + c) / (d + 1e-6f);
    }
}

extern "C" void kernel_launch(void* const* d_in, const int* in_sizes, int n_in,
                              void* d_out, int out_size) {
    (void)in_sizes; (void)n_in; (void)out_size;
    const float* im  = (const float*)d_in[0];
    const float* dis = (const float*)d_in[1];
    const void*  lbl = d_in[2];

    cudaFuncSetAttribute(fused_kernel, cudaFuncAttributeMaxDynamicSharedMemorySize, SMEM_BYTES);
    dim3 grid(P_ / TILE_M, B_);
    fused_kernel<<<grid, 256, SMEM_BYTES>>>(im, dis, lbl, (float*)d_out);
}

// round 10
// speedup vs baseline: 2.1103x; 1.0384x over previous
#include <cuda_runtime.h>
#include <cstdint>

#define B_  64
#define P_  2048
#define D_  1024
#define TILE_M 128
#define KC 32
#define NSTAGE (D_ / KC)        /* 32 stages */
#define PITCH 144               /* 9 16B-units/row, odd mod 8 -> ldmatrix conflict-free */
#define A_OFF 0
#define B_OFF (TILE_M * PITCH)  /* 18432 */
#define STAGE_B 27648           /* one buffer: A 18432 + B 9216 */
#define SMEM_BYTES (2 * STAGE_B)           /* 55296 dynamic */
#define NCTAS ((P_ / TILE_M) * B_)         /* 1024 */

__device__ unsigned int g_key[B_ * B_];    /* order-preserving keys; 0 == -inf */
__device__ unsigned int g_count;           /* last-CTA counter; resets itself  */

__device__ __forceinline__ uint32_t smem_u32(const void* p) {
    uint32_t a;
    asm("{ .reg .u64 t; cvta.to.shared.u64 t, %1; cvt.u32.u64 %0, t; }" : "=r"(a) : "l"(p));
    return a;
}
__device__ __forceinline__ uint32_t pack_bf16x2(float lo_e, float hi_e) {
    uint32_t h;
    asm("cvt.rn.bf16x2.f32 %0, %1, %2;" : "=r"(h) : "f"(hi_e), "f"(lo_e));
    return h;
}
/* one float4 (k 4p..4p+3) -> hi 8B @hiA, lo 8B @hiA+16 (next 16B unit) */
__device__ __forceinline__ void cvt_sts4(uint32_t hiA, float4 v) {
    uint32_t h0 = pack_bf16x2(v.x, v.y);
    uint32_t h1 = pack_bf16x2(v.z, v.w);
    uint32_t l0 = pack_bf16x2(v.x - __uint_as_float(h0 << 16),
                              v.y - __uint_as_float(h0 & 0xFFFF0000u));
    uint32_t l1 = pack_bf16x2(v.z - __uint_as_float(h1 << 16),
                              v.w - __uint_as_float(h1 & 0xFFFF0000u));
    asm volatile("st.shared.v2.b32 [%0], {%1,%2};" :: "r"(hiA), "r"(h0), "r"(h1) : "memory");
    asm volatile("st.shared.v2.b32 [%0], {%1,%2};" :: "r"(hiA + 16), "r"(l0), "r"(l1) : "memory");
}
__device__ __forceinline__ void ldsm4(uint32_t* r, uint32_t addr) {
    asm volatile("ldmatrix.sync.aligned.m8n8.x4.shared.b16 {%0,%1,%2,%3}, [%4];"
                 : "=r"(r[0]), "=r"(r[1]), "=r"(r[2]), "=r"(r[3]) : "r"(addr));
}
__device__ __forceinline__ void mma16816(float* c, const uint32_t* a, const uint32_t* b) {
    asm volatile(
        "mma.sync.aligned.m16n8k16.row.col.f32.bf16.bf16.f32 "
        "{%0,%1,%2,%3}, {%4,%5,%6,%7}, {%8,%9}, {%0,%1,%2,%3};"
        : "+f"(c[0]), "+f"(c[1]), "+f"(c[2]), "+f"(c[3])
        : "r"(a[0]), "r"(a[1]), "r"(a[2]), "r"(a[3]), "r"(b[0]), "r"(b[1]));
}

/* Grid (16,64), 256 thr. sim[128p x 64c] split-bf16 HMMA, double-buffered smem.
   Warp-phase staggering: even warps stage->compute, odd warps compute->stage,
   so MIO (STS/LDSM/LDG) and tensor pipes overlap across warps instead of
   saturating alternately in lockstep. */
__global__ __launch_bounds__(256, 2)
void fused_kernel(const float* __restrict__ im, const float* __restrict__ dis,
                  const void* __restrict__ lblRaw, float* __restrict__ out) {
    extern __shared__ __align__(128) char smem[];
    __shared__ int s_last, s_is64;
    __shared__ float rr[3][8];
    const uint32_t sb = smem_u32(smem);
    const int tid = threadIdx.x, lid = tid & 31, wid = tid >> 5;
    const int wm = wid & 3, wn = wid >> 2;
    const int b = blockIdx.y, pt = blockIdx.x;

    /* staging: row = tid>>3, part p = tid&7; 8 lanes cover one 128B gmem line */
    const int r0 = tid >> 3, p0 = tid & 7;
    const float* aG = im + ((size_t)(b * P_ + pt * TILE_M + r0)) * D_ + p0 * 4;
    const float* bG = dis + (size_t)r0 * D_ + p0 * 4;
    const uint32_t aS = sb + A_OFF + (uint32_t)(r0 * PITCH + (p0 >> 1) * 32 + (p0 & 1) * 8);
    const uint32_t bS = sb + B_OFF + (uint32_t)(r0 * PITCH + (p0 >> 1) * 32 + (p0 & 1) * 8);

    /* ldmatrix lane bases (hi unit; lo = +16; k-octet-high = +32; sub s = +s*64) */
    const uint32_t aLd = sb + A_OFF + (uint32_t)((wm * 32 + (lid & 15)) * PITCH + (lid >> 4) * 32);
    const uint32_t bLd = sb + B_OFF + (uint32_t)((wn * 32 + (lid >> 4) * 8 + (lid & 7)) * PITCH
                                                 + ((lid >> 3) & 1) * 32);
    float acc[2][4][4];
    #pragma unroll
    for (int i = 0; i < 2; ++i)
        #pragma unroll
        for (int j = 0; j < 4; ++j)
            #pragma unroll
            for (int k = 0; k < 4; ++k) acc[i][j][k] = 0.f;

    float4 va[4], vb[2];
    const int sflip = (wid >> 1) & 1;   /* per-warp-pair sub-chunk order */

    /* staging helpers (warp-uniform call sites) */
    auto do_sts = [&](uint32_t nxt) {
        #pragma unroll
        for (int j = 0; j < 4; ++j) cvt_sts4(nxt + aS + j * 32 * PITCH, va[j]);
        #pragma unroll
        for (int j = 0; j < 2; ++j) cvt_sts4(nxt + bS + j * 32 * PITCH, vb[j]);
    };
    auto do_ldg = [&](int kt2) {
        const float* a2 = aG + kt2 * KC;
        const float* b2 = bG + kt2 * KC;
        #pragma unroll
        for (int j = 0; j < 4; ++j) va[j] = *(const float4*)(a2 + j * 32 * D_);
        #pragma unroll
        for (int j = 0; j < 2; ++j) vb[j] = *(const float4*)(b2 + j * 32 * D_);
    };
    auto do_mma = [&](uint32_t cur) {
        #pragma unroll
        for (int si = 0; si < 2; ++si) {
            const int s = si ^ sflip;
            uint32_t Ah[2][4], Al[2][4], Bh[2][4], Bl[2][4];
            #pragma unroll
            for (int mt = 0; mt < 2; ++mt) {
                ldsm4(Ah[mt], cur + aLd + mt * (16 * PITCH) + s * 64);
                ldsm4(Al[mt], cur + aLd + mt * (16 * PITCH) + s * 64 + 16);
            }
            #pragma unroll
            for (int h = 0; h < 2; ++h) {
                ldsm4(Bh[h], cur + bLd + h * (16 * PITCH) + s * 64);
                ldsm4(Bl[h], cur + bLd + h * (16 * PITCH) + s * 64 + 16);
            }
            #pragma unroll
            for (int mt = 0; mt < 2; ++mt)
                #pragma unroll
                for (int nt = 0; nt < 4; ++nt)
                    mma16816(acc[mt][nt], Ah[mt], &Bh[nt >> 1][(nt & 1) * 2]);
            #pragma unroll
            for (int mt = 0; mt < 2; ++mt)
                #pragma unroll
                for (int nt = 0; nt < 4; ++nt)
                    mma16816(acc[mt][nt], Ah[mt], &Bl[nt >> 1][(nt & 1) * 2]);
            #pragma unroll
            for (int mt = 0; mt < 2; ++mt)
                #pragma unroll
                for (int nt = 0; nt < 4; ++nt)
                    mma16816(acc[mt][nt], Al[mt], &Bh[nt >> 1][(nt & 1) * 2]);
        }
    };

    /* prologue: stage 0 -> buf0; prefetch stage 1 into regs */
    do_ldg(0);
    do_sts(0);
    do_ldg(1);
    __syncthreads();

    for (int kt = 0; kt < NSTAGE; ++kt) {
        const uint32_t cur = (uint32_t)((kt & 1) * STAGE_B);
        const uint32_t nxt = (uint32_t)(((kt + 1) & 1) * STAGE_B);
        const bool haveN = (kt + 1 < NSTAGE);
        const bool haveN2 = (kt + 2 < NSTAGE);

        if ((wid & 1) == 0) {       /* even warps: stage first, compute second */
            if (haveN)  do_sts(nxt);
            if (haveN2) do_ldg(kt + 2);
            do_mma(cur);
        } else {                    /* odd warps: compute first, stage second */
            do_mma(cur);
            if (haveN)  do_sts(nxt);
            if (haveN2) do_ldg(kt + 2);
        }
        __syncthreads();   /* reads of cur done; writes to nxt visible */
    }

    /* epilogue: fragments -> smem -> per-column max -> atomicMax */
    float* red = (float*)smem;   /* [128][66] = 33792 <= 55296 */
    const int g = lid >> 2, t = lid & 3;
    #pragma unroll
    for (int mt = 0; mt < 2; ++mt) {
        const int rr0 = wm * 32 + mt * 16 + g;
        #pragma unroll
        for (int nt = 0; nt < 4; ++nt) {
            const int c = wn * 32 + nt * 8 + t * 2;
            red[rr0 * 66 + c]           = acc[mt][nt][0];
            red[rr0 * 66 + c + 1]       = acc[mt][nt][1];
            red[(rr0 + 8) * 66 + c]     = acc[mt][nt][2];
            red[(rr0 + 8) * 66 + c + 1] = acc[mt][nt][3];
        }
    }
    __syncthreads();
    if (tid < 64) {
        float m = -3.4e38f;
        #pragma unroll 8
        for (int r = 0; r < TILE_M; ++r) m = fmaxf(m, red[r * 66 + tid]);
        unsigned int k = __float_as_uint(m);
        k = (k & 0x80000000u) ? ~k : (k | 0x80000000u);
        atomicMax(&g_key[b * B_ + tid], k);
    }
    __syncthreads();
    if (tid == 0) {
        __threadfence();
        s_last = (atomicAdd(&g_count, 1u) == NCTAS - 1);
    }
    __syncthreads();
    if (!s_last) return;
    __threadfence();   /* acquire: all producers' g_key writes now visible */

    /* ---- last CTA: decode simMax, hinge loss, reset globals ---- */
    float* sm = (float*)smem;          /* [64][65] */
    int*   lab = (int*)(smem + 64 * 65 * 4);
    for (int e = tid; e < B_ * B_; e += 256) {
        const unsigned int u = g_key[e];
        sm[(e >> 6) * 65 + (e & 63)] =
            __uint_as_float((u & 0x80000000u) ? (u ^ 0x80000000u) : ~u);
    }
    if (tid < 32) {   /* int64 labels (values <64) have zero odd int32 words */
        int odd = ((const int*)lblRaw)[2 * tid + 1];
        unsigned mm = __ballot_sync(0xFFFFFFFFu, odd != 0);
        if (tid == 0) s_is64 = (mm == 0u);
    }
    __syncthreads();
    if (tid < B_)
        lab[tid] = s_is64 ? (int)((const long long*)lblRaw)[tid] : ((const int*)lblRaw)[tid];
    __syncthreads();
    for (int e = tid; e < B_ * B_; e += 256) g_key[e] = 0u;   /* reset */
    if (tid == 0) g_count = 0u;

    float s1 = 0.f, s2 = 0.f, n = 0.f;
    for (int e = tid; e < B_ * B_; e += 256) {
        const int i = e >> 6, j = e & 63;
        if (lab[i] != lab[j]) {
            n += 1.f;
            const float p = sm[i * 65 + i];
            s1 += fmaxf(sm[i * 65 + j] - p + 0.1f, 0.f);
            s2 += fmaxf(sm[j * 65 + i] - p + 0.1f, 0.f);
        }
    }
    #pragma unroll
    for (int o = 16; o > 0; o >>= 1) {
        s1 += __shfl_down_sync(0xFFFFFFFFu, s1, o);
        s2 += __shfl_down_sync(0xFFFFFFFFu, s2, o);
        n  += __shfl_down_sync(0xFFFFFFFFu, n,  o);
    }
    if (lid == 0) { rr[0][wid] = s1; rr[1][wid] = s2; rr[2][wid] = n; }
    __syncthreads();
    if (tid == 0) {
        float a = 0.f, c = 0.f, d = 0.f;
        #pragma unroll
        for (int w = 0; w < 8; ++w) { a += rr[0][w]; c += rr[1][w]; d += rr[2][w]; }
        out[0] = (a + c) / (d + 1e-6f);
    }
}

extern "C" void kernel_launch(void* const* d_in, const int* in_sizes, int n_in,
                              void* d_out, int out_size) {
    (void)in_sizes; (void)n_in; (void)out_size;
    const float* im  = (const float*)d_in[0];
    const float* dis = (const float*)d_in[1];
    const void*  lbl = d_in[2];

    cudaFuncSetAttribute(fused_kernel, cudaFuncAttributeMaxDynamicSharedMemorySize, SMEM_BYTES);
    dim3 grid(P_ / TILE_M, B_);
    fused_kernel<<<grid, 256, SMEM_BYTES>>>(im, dis, lbl, (float*)d_out);
}